// round 3
// baseline (speedup 1.0000x reference)
#include <cuda_runtime.h>
#include <math.h>

#define BATCH 4
#define CH    96
#define HRES  256
#define WRES  256
#define HW    65536
#define HEADS 3
#define HD    32
#define NPOS  64
#define NWIN  4096
#define QSCALE 0.17677669529663687f

typedef unsigned long long ull;

// packed fp32x2 helpers (sm_100+/sm_103a: FFMA2 only reachable via PTX)
#define FFMA2(d, a, b, c) \
    asm("fma.rn.f32x2 %0, %1, %2, %3;" : "=l"(d) : "l"(a), "l"(b), "l"(c))
#define PACK2(out, lo, hi) \
    asm("mov.b64 %0, {%1, %2};" : "=l"(out) : "f"(lo), "f"(hi))
#define UNPACK2(lo, hi, in) \
    asm("mov.b64 {%0, %1}, %2;" : "=f"(lo), "=f"(hi) : "l"(in))

// ---------------- scratch (device globals; no runtime allocation) ----------
__device__ float g_V   [BATCH*CH*HW];          // V in NCHW (input to depthwise)
__device__ float g_conv[BATCH*CH*HW];          // depthwise output, NCHW
__device__ float g_q   [NWIN*HEADS*HD*NPOS];   // [win][head][d][n], pre-scaled
__device__ float g_k   [NWIN*HEADS*HD*NPOS];   // [win][head][d][m]
__device__ float g_v   [NWIN*HEADS*NPOS*HD];   // [win][head][m][d]  (transposed!)
__device__ float g_att [BATCH*HW*CH];          // attention out, channels-last
__device__ float g_bias[HEADS*NPOS*NPOS];      // TRANSPOSED: [head][m][n]

// ---------------- kernel B: bias MLP table (stores [h][m][n]) --------------
__global__ void bias_kernel(const float* __restrict__ Wm1, const float* __restrict__ bm1,
                            const float* __restrict__ Wm2, const float* __restrict__ bm2)
{
    int gid = blockIdx.x * 256 + threadIdx.x;
    int n = gid >> 6, m = gid & 63;
    float r0 = (float)((n >> 3) - (m >> 3));
    float r1 = (float)((n & 7)  - (m & 7));
    r0 = copysignf(log1pf(fabsf(r0)), r0);
    r1 = copysignf(log1pf(fabsf(r1)), r1);
    float a0 = bm2[0], a1 = bm2[1], a2 = bm2[2];
    for (int j = 0; j < 256; j++) {
        float h = fmaf(r0, Wm1[j], fmaf(r1, Wm1[256 + j], bm1[j]));
        h = fmaxf(h, 0.f);
        a0 = fmaf(h, Wm2[j*3 + 0], a0);
        a1 = fmaf(h, Wm2[j*3 + 1], a1);
        a2 = fmaf(h, Wm2[j*3 + 2], a2);
    }
    int ti = m*64 + n;                  // transposed index
    g_bias[0*4096 + ti] = a0;
    g_bias[1*4096 + ti] = a1;
    g_bias[2*4096 + ti] = a2;
}

// ---------------- kernel A: fused QKV 1x1 conv GEMM (f32x2) ----------------
__global__ __launch_bounds__(128) void qkv_kernel(
    const float* __restrict__ x,
    const float* __restrict__ Wqk, const float* __restrict__ bqk,
    const float* __restrict__ Wv,  const float* __restrict__ bv)
{
    __shared__ __align__(16) float x_s[96][64];
    __shared__ float w_s[96][49];

    int t   = blockIdx.x;
    int b   = t >> 10;
    int hw0 = (t & 1023) << 6;
    int ch0 = blockIdx.y * 48;
    int tid = threadIdx.x;

    for (int idx = tid; idx < 96*16; idx += 128) {
        int k = idx >> 4, p4 = idx & 15;
        *(float4*)&x_s[k][p4*4] = *(const float4*)&x[(b*96 + k)*HW + hw0 + p4*4];
    }
    for (int idx = tid; idx < 96*48; idx += 128) {
        int k = idx % 96, c = idx / 96;
        int o = ch0 + c;
        w_s[k][c] = (o < 192) ? Wqk[o*96 + k] : Wv[(o - 192)*96 + k];
    }
    __syncthreads();

    int pxg = tid & 15, chg = tid >> 4;
    int cb  = chg * 6;
    ull acc2[6][2];
    #pragma unroll
    for (int i = 0; i < 6; i++) { acc2[i][0] = 0ULL; acc2[i][1] = 0ULL; }

    #pragma unroll 4
    for (int k = 0; k < 96; k++) {
        ulonglong2 xv = *(const ulonglong2*)&x_s[k][pxg*4];
        #pragma unroll
        for (int i = 0; i < 6; i++) {
            float wv = w_s[k][cb + i];
            ull w2; PACK2(w2, wv, wv);
            FFMA2(acc2[i][0], w2, xv.x, acc2[i][0]);
            FFMA2(acc2[i][1], w2, xv.y, acc2[i][1]);
        }
    }

    int p0 = pxg * 4;
    int hw = hw0 + p0;
    int h  = hw >> 8, w = hw & 255;
    int hp = (h + 252) & 255;
    int wp = (w + 252) & 255;
    int wh = hp >> 3, r = hp & 7, ww = wp >> 3, cc = wp & 7;
    int win = b*1024 + wh*32 + ww;
    int n   = r*8 + cc;
    int grp = ch0 / 96;

    #pragma unroll
    for (int ci = 0; ci < 6; ci++) {
        int o = ch0 + cb + ci;
        float bia = (o < 192) ? bqk[o] : bv[o - 192];
        float a0, a1, a2, a3;
        UNPACK2(a0, a1, acc2[ci][0]);
        UNPACK2(a2, a3, acc2[ci][1]);
        float4 v4 = make_float4(a0 + bia, a1 + bia, a2 + bia, a3 + bia);
        int cg = o % 96;
        int head = cg >> 5, d = cg & 31;
        if (grp == 0) {
            int qi = ((win*3 + head)*32 + d)*64 + n;
            *(float4*)&g_q[qi] = make_float4(v4.x*QSCALE, v4.y*QSCALE,
                                             v4.z*QSCALE, v4.w*QSCALE);
        } else if (grp == 1) {
            int ki = ((win*3 + head)*32 + d)*64 + n;
            *(float4*)&g_k[ki] = v4;
        } else {
            int vi = ((win*3 + head)*64 + n)*32 + d;   // transposed [m][d]
            g_v[vi]      = v4.x;
            g_v[vi + 32] = v4.y;
            g_v[vi + 64] = v4.z;
            g_v[vi + 96] = v4.w;
            *(float4*)&g_V[(b*96 + cg)*HW + hw] = v4;
        }
    }
}

// ---------------- kernel DW: depthwise 5x5, reflect, smem halo -------------
__global__ __launch_bounds__(256) void dw_kernel(const float* __restrict__ Wdw,
                                                 const float* __restrict__ bdw)
{
    __shared__ float s[36][37];
    __shared__ float wk[25];

    int blk  = blockIdx.x;
    int img  = blk >> 6;
    int tile = blk & 63;
    int c    = img % 96;
    int h0   = (tile >> 3) << 5, w0 = (tile & 7) << 5;
    int tid  = threadIdx.x;

    if (tid < 25) wk[tid] = Wdw[c*25 + tid];
    const float* vimg = g_V + (size_t)img * HW;
    for (int idx = tid; idx < 36*36; idx += 256) {
        int r  = idx / 36, cc = idx % 36;
        int hh = h0 - 2 + r;  hh = (hh < 0) ? -hh : ((hh > 255) ? 510 - hh : hh);
        int wq = w0 - 2 + cc; wq = (wq < 0) ? -wq : ((wq > 255) ? 510 - wq : wq);
        s[r][cc] = vimg[hh*256 + wq];
    }
    __syncthreads();

    float b0 = bdw[c];
    #pragma unroll
    for (int kq = 0; kq < 4; kq++) {
        int px = tid + kq*256;
        int y = px >> 5, xq = px & 31;
        float acc = b0;
        #pragma unroll
        for (int i = 0; i < 5; i++)
            #pragma unroll
            for (int j = 0; j < 5; j++)
                acc = fmaf(s[y + i][xq + j], wk[i*5 + j], acc);
        g_conv[(size_t)img*HW + (h0 + y)*256 + (w0 + xq)] = acc;
    }
}

// ---------------- kernel C: windowed attention (online softmax, f32x2) -----
__device__ __forceinline__ int swin_label(int wh, int ww, int idx) {
    int rh = (wh == 31) ? (1 + (((idx >> 3) >= 4) ? 1 : 0)) : 0;
    int rw = (ww == 31) ? (1 + (((idx & 7)  >= 4) ? 1 : 0)) : 0;
    return rh*3 + rw;
}

__global__ __launch_bounds__(64) void attn_kernel()
{
    __shared__ __align__(16) float k_s[2048];   // [d][m]
    __shared__ __align__(16) float v_s[2048];   // [m][d]

    int win  = blockIdx.x;
    int head = blockIdx.y;
    int n    = threadIdx.x;
    size_t base = (size_t)(win*3 + head) * 2048;

    for (int idx = n; idx < 512; idx += 64) {
        ((float4*)k_s)[idx] = ((const float4*)(g_k + base))[idx];
        ((float4*)v_s)[idx] = ((const float4*)(g_v + base))[idx];
    }
    ull qq[32];
    const float* qp = g_q + base;
    #pragma unroll
    for (int d = 0; d < 32; d++) {
        float qv = qp[d*64 + n];
        PACK2(qq[d], qv, qv);
    }
    __syncthreads();

    int wloc = win & 1023;
    int wh = wloc >> 5, ww = wloc & 31;
    bool masked = (wh == 31) || (ww == 31);
    int labn = masked ? swin_label(wh, ww, n) : 0;

    const float* brow = g_bias + head*4096 + n;   // transposed: [m][n]

    float l = 0.f;
    ull out2[16];
    #pragma unroll
    for (int j = 0; j < 16; j++) out2[j] = 0ULL;

    #pragma unroll 1
    for (int mc = 0; mc < 64; mc += 8) {
        ull s2[4] = {0ULL, 0ULL, 0ULL, 0ULL};
        #pragma unroll
        for (int d = 0; d < 32; d++) {
            ulonglong2 kk0 = *(const ulonglong2*)&k_s[d*64 + mc];
            ulonglong2 kk1 = *(const ulonglong2*)&k_s[d*64 + mc + 4];
            FFMA2(s2[0], qq[d], kk0.x, s2[0]);
            FFMA2(s2[1], qq[d], kk0.y, s2[1]);
            FFMA2(s2[2], qq[d], kk1.x, s2[2]);
            FFMA2(s2[3], qq[d], kk1.y, s2[3]);
        }
        float p[8];
        #pragma unroll
        for (int i2 = 0; i2 < 4; i2++) {
            float lo, hi;
            UNPACK2(lo, hi, s2[i2]);
            float b0 = brow[(mc + 2*i2    )*64];
            float b1 = brow[(mc + 2*i2 + 1)*64];
            p[2*i2    ] = __expf(lo + b0);
            p[2*i2 + 1] = __expf(hi + b1);
        }
        if (masked) {
            #pragma unroll
            for (int i = 0; i < 8; i++)
                if (swin_label(wh, ww, mc + i) != labn) p[i] = 0.f;
        }
        #pragma unroll
        for (int i = 0; i < 8; i++) l += p[i];

        #pragma unroll
        for (int i = 0; i < 8; i++) {
            ull pp; PACK2(pp, p[i], p[i]);
            const ulonglong2* vr = (const ulonglong2*)&v_s[(mc + i)*32];
            #pragma unroll
            for (int j = 0; j < 8; j++) {
                ulonglong2 vv = vr[j];
                FFMA2(out2[2*j    ], pp, vv.x, out2[2*j    ]);
                FFMA2(out2[2*j + 1], pp, vv.y, out2[2*j + 1]);
            }
        }
    }

    float inv = 1.f / l;
    float o[32];
    #pragma unroll
    for (int j = 0; j < 16; j++) UNPACK2(o[2*j], o[2*j + 1], out2[j]);

    int b = win >> 10;
    int r = n >> 3, c = n & 7;
    int h = ((wh << 3) + r + 4) & 255;
    int w = ((ww << 3) + c + 4) & 255;
    float* ap = g_att + ((size_t)(b*256 + h)*256 + w)*96 + head*32;
    #pragma unroll
    for (int d = 0; d < 32; d += 4) {
        *(float4*)&ap[d] = make_float4(o[d]*inv, o[d+1]*inv,
                                       o[d+2]*inv, o[d+3]*inv);
    }
}

// ---------------- kernel D: add (conv + attn), final 96x96 GEMM (f32x2) ----
__global__ __launch_bounds__(256) void final_kernel(
    const float* __restrict__ Wp, const float* __restrict__ bp,
    float* __restrict__ outp)
{
    __shared__ float t_s[64][97];
    __shared__ __align__(16) float w_s[32][98];   // even stride for LDS.64

    int t   = blockIdx.x;
    int b   = t >> 10;
    int hw0 = (t & 1023) << 6;
    int h   = hw0 >> 8;
    int tid = threadIdx.x;

    for (int idx = tid; idx < 96*16; idx += 256) {
        int c = idx >> 4, pq = idx & 15;
        float4 v4 = *(const float4*)&g_conv[((size_t)b*96 + c)*HW + hw0 + pq*4];
        t_s[pq*4 + 0][c] = v4.x;
        t_s[pq*4 + 1][c] = v4.y;
        t_s[pq*4 + 2][c] = v4.z;
        t_s[pq*4 + 3][c] = v4.w;
    }
    __syncthreads();

    const float* ab = g_att + ((size_t)(b*256 + h)*256 + (hw0 & 255))*96;
    for (int idx = tid; idx < 64*24; idx += 256) {
        int f4 = idx % 24, p = idx / 24;
        float4 a4 = *(const float4*)&ab[p*96 + f4*4];
        int c = f4*4;
        t_s[p][c]     += a4.x;
        t_s[p][c + 1] += a4.y;
        t_s[p][c + 2] += a4.z;
        t_s[p][c + 3] += a4.w;
    }
    __syncthreads();

    int pxg = tid & 15, chg = tid >> 4;
    int p0 = pxg*4, ob = chg*6;
    ull acc2[3][4];
    #pragma unroll
    for (int i = 0; i < 3; i++)
        #pragma unroll
        for (int j = 0; j < 4; j++) acc2[i][j] = 0ULL;

    for (int kc = 0; kc < 3; kc++) {
        if (kc) __syncthreads();
        for (int idx = tid; idx < 32*96; idx += 256) {
            int kk = idx & 31, o = idx >> 5;
            w_s[kk][o] = Wp[o*96 + kc*32 + kk];
        }
        __syncthreads();
        #pragma unroll 4
        for (int kk = 0; kk < 32; kk++) {
            int k = kc*32 + kk;
            float tv0 = t_s[p0][k],   tv1 = t_s[p0+1][k];
            float tv2 = t_s[p0+2][k], tv3 = t_s[p0+3][k];
            ull tt0, tt1, tt2, tt3;
            PACK2(tt0, tv0, tv0); PACK2(tt1, tv1, tv1);
            PACK2(tt2, tv2, tv2); PACK2(tt3, tv3, tv3);
            #pragma unroll
            for (int i = 0; i < 3; i++) {
                ull w2 = *(const ull*)&w_s[kk][ob + 2*i];
                FFMA2(acc2[i][0], w2, tt0, acc2[i][0]);
                FFMA2(acc2[i][1], w2, tt1, acc2[i][1]);
                FFMA2(acc2[i][2], w2, tt2, acc2[i][2]);
                FFMA2(acc2[i][3], w2, tt3, acc2[i][3]);
            }
        }
    }

    #pragma unroll
    for (int i = 0; i < 3; i++) {
        int o0 = ob + 2*i, o1 = o0 + 1;
        float bo0 = bp[o0], bo1 = bp[o1];
        float lo[4], hi[4];
        #pragma unroll
        for (int j = 0; j < 4; j++) UNPACK2(lo[j], hi[j], acc2[i][j]);
        *(float4*)&outp[((size_t)b*96 + o0)*HW + hw0 + p0] =
            make_float4(lo[0] + bo0, lo[1] + bo0, lo[2] + bo0, lo[3] + bo0);
        *(float4*)&outp[((size_t)b*96 + o1)*HW + hw0 + p0] =
            make_float4(hi[0] + bo1, hi[1] + bo1, hi[2] + bo1, hi[3] + bo1);
    }
}

// ---------------- launch ----------------------------------------------------
extern "C" void kernel_launch(void* const* d_in, const int* in_sizes, int n_in,
                              void* d_out, int out_size)
{
    const float* x   = (const float*)d_in[0];
    const float* Wv  = (const float*)d_in[1];
    const float* bv  = (const float*)d_in[2];
    const float* Wqk = (const float*)d_in[3];
    const float* bqk = (const float*)d_in[4];
    const float* Wm1 = (const float*)d_in[5];
    const float* bm1 = (const float*)d_in[6];
    const float* Wm2 = (const float*)d_in[7];
    const float* bm2 = (const float*)d_in[8];
    const float* Wdw = (const float*)d_in[9];
    const float* bdw = (const float*)d_in[10];
    const float* Wp  = (const float*)d_in[11];
    const float* bp  = (const float*)d_in[12];
    float* outp = (float*)d_out;

    bias_kernel <<<16, 256>>>(Wm1, bm1, Wm2, bm2);
    qkv_kernel  <<<dim3(4096, 6), 128>>>(x, Wqk, bqk, Wv, bv);
    dw_kernel   <<<24576, 256>>>(Wdw, bdw);
    attn_kernel <<<dim3(4096, 3), 64>>>();
    final_kernel<<<4096, 256>>>(Wp, bp, outp);
}

// round 4
// speedup vs baseline: 1.3755x; 1.3755x over previous
#include <cuda_runtime.h>
#include <math.h>

#define BATCH 4
#define CH    96
#define HRES  256
#define WRES  256
#define HW    65536
#define HEADS 3
#define HD    32
#define NPOS  64
#define NWIN  4096
#define QSCALE 0.17677669529663687f

// ---------------- scratch (device globals; no runtime allocation) ----------
__device__ float g_V   [BATCH*CH*HW];          // V in NCHW (input to depthwise)
__device__ float g_conv[BATCH*CH*HW];          // depthwise output, NCHW
__device__ float g_q   [NWIN*HEADS*HD*NPOS];   // [win][head][d][n], pre-scaled
__device__ float g_k   [NWIN*HEADS*HD*NPOS];   // [win][head][d][m]
__device__ float g_v   [NWIN*HEADS*NPOS*HD];   // [win][head][m][d]  (transposed)
__device__ float g_att [BATCH*HW*CH];          // attention out, channels-last
__device__ float g_bias[HEADS*NPOS*NPOS];      // [head][n][m]

// ---------------- kernel B: bias MLP table ---------------------------------
__global__ void bias_kernel(const float* __restrict__ Wm1, const float* __restrict__ bm1,
                            const float* __restrict__ Wm2, const float* __restrict__ bm2)
{
    int gid = blockIdx.x * 256 + threadIdx.x;
    int n = gid >> 6, m = gid & 63;
    float r0 = (float)((n >> 3) - (m >> 3));
    float r1 = (float)((n & 7)  - (m & 7));
    r0 = copysignf(log1pf(fabsf(r0)), r0);
    r1 = copysignf(log1pf(fabsf(r1)), r1);
    float a0 = bm2[0], a1 = bm2[1], a2 = bm2[2];
    for (int j = 0; j < 256; j++) {
        float h = fmaf(r0, Wm1[j], fmaf(r1, Wm1[256 + j], bm1[j]));
        h = fmaxf(h, 0.f);
        a0 = fmaf(h, Wm2[j*3 + 0], a0);
        a1 = fmaf(h, Wm2[j*3 + 1], a1);
        a2 = fmaf(h, Wm2[j*3 + 2], a2);
    }
    g_bias[0*4096 + gid] = a0;
    g_bias[1*4096 + gid] = a1;
    g_bias[2*4096 + gid] = a2;
}

// ---------------- kernel A: fused QKV 1x1 conv GEMM ------------------------
__global__ __launch_bounds__(128) void qkv_kernel(
    const float* __restrict__ x,
    const float* __restrict__ Wqk, const float* __restrict__ bqk,
    const float* __restrict__ Wv,  const float* __restrict__ bv)
{
    __shared__ __align__(16) float x_s[96][64];
    __shared__ float w_s[96][49];

    int t   = blockIdx.x;
    int b   = t >> 10;
    int hw0 = (t & 1023) << 6;
    int ch0 = blockIdx.y * 48;
    int tid = threadIdx.x;

    for (int idx = tid; idx < 96*16; idx += 128) {
        int k = idx >> 4, p4 = idx & 15;
        *(float4*)&x_s[k][p4*4] = *(const float4*)&x[(b*96 + k)*HW + hw0 + p4*4];
    }
    for (int idx = tid; idx < 96*48; idx += 128) {
        int k = idx % 96, c = idx / 96;
        int o = ch0 + c;
        w_s[k][c] = (o < 192) ? Wqk[o*96 + k] : Wv[(o - 192)*96 + k];
    }
    __syncthreads();

    int pxg = tid & 15, chg = tid >> 4;
    int cb  = chg * 6;
    float acc[6][4];
    #pragma unroll
    for (int i = 0; i < 6; i++)
        #pragma unroll
        for (int j = 0; j < 4; j++) acc[i][j] = 0.f;

    #pragma unroll 4
    for (int k = 0; k < 96; k++) {
        float4 xv = *(const float4*)&x_s[k][pxg*4];
        #pragma unroll
        for (int i = 0; i < 6; i++) {
            float wv = w_s[k][cb + i];
            acc[i][0] = fmaf(wv, xv.x, acc[i][0]);
            acc[i][1] = fmaf(wv, xv.y, acc[i][1]);
            acc[i][2] = fmaf(wv, xv.z, acc[i][2]);
            acc[i][3] = fmaf(wv, xv.w, acc[i][3]);
        }
    }

    int p0 = pxg * 4;
    int hw = hw0 + p0;
    int h  = hw >> 8, w = hw & 255;
    int hp = (h + 252) & 255;
    int wp = (w + 252) & 255;
    int wh = hp >> 3, r = hp & 7, ww = wp >> 3, cc = wp & 7;
    int win = b*1024 + wh*32 + ww;
    int n   = r*8 + cc;
    int grp = ch0 / 96;

    #pragma unroll
    for (int ci = 0; ci < 6; ci++) {
        int o = ch0 + cb + ci;
        float bia = (o < 192) ? bqk[o] : bv[o - 192];
        float4 v4 = make_float4(acc[ci][0] + bia, acc[ci][1] + bia,
                                acc[ci][2] + bia, acc[ci][3] + bia);
        int cg = o % 96;
        int head = cg >> 5, d = cg & 31;
        if (grp == 0) {
            int qi = ((win*3 + head)*32 + d)*64 + n;
            *(float4*)&g_q[qi] = make_float4(v4.x*QSCALE, v4.y*QSCALE,
                                             v4.z*QSCALE, v4.w*QSCALE);
        } else if (grp == 1) {
            int ki = ((win*3 + head)*32 + d)*64 + n;
            *(float4*)&g_k[ki] = v4;
        } else {
            int vi = ((win*3 + head)*64 + n)*32 + d;   // transposed [m][d]
            g_v[vi]      = v4.x;
            g_v[vi + 32] = v4.y;
            g_v[vi + 64] = v4.z;
            g_v[vi + 96] = v4.w;
            *(float4*)&g_V[(b*96 + cg)*HW + hw] = v4;
        }
    }
}

// ---------------- kernel DW: depthwise 5x5, reflect, smem halo -------------
__global__ __launch_bounds__(256) void dw_kernel(const float* __restrict__ Wdw,
                                                 const float* __restrict__ bdw)
{
    __shared__ float s[36][37];
    __shared__ float wk[25];

    int blk  = blockIdx.x;
    int img  = blk >> 6;
    int tile = blk & 63;
    int c    = img % 96;
    int h0   = (tile >> 3) << 5, w0 = (tile & 7) << 5;
    int tid  = threadIdx.x;

    if (tid < 25) wk[tid] = Wdw[c*25 + tid];
    const float* vimg = g_V + (size_t)img * HW;
    for (int idx = tid; idx < 36*36; idx += 256) {
        int r  = idx / 36, cc = idx % 36;
        int hh = h0 - 2 + r;  hh = (hh < 0) ? -hh : ((hh > 255) ? 510 - hh : hh);
        int wq = w0 - 2 + cc; wq = (wq < 0) ? -wq : ((wq > 255) ? 510 - wq : wq);
        s[r][cc] = vimg[hh*256 + wq];
    }
    __syncthreads();

    float b0 = bdw[c];
    #pragma unroll
    for (int kq = 0; kq < 4; kq++) {
        int px = tid + kq*256;
        int y = px >> 5, xq = px & 31;
        float acc = b0;
        #pragma unroll
        for (int i = 0; i < 5; i++)
            #pragma unroll
            for (int j = 0; j < 5; j++)
                acc = fmaf(s[y + i][xq + j], wk[i*5 + j], acc);
        g_conv[(size_t)img*HW + (h0 + y)*256 + (w0 + xq)] = acc;
    }
}

// ---------------- kernel C: attention, register-blocked GEMMs --------------
__device__ __forceinline__ int swin_label(int wh, int ww, int idx) {
    int rh = (wh == 31) ? (1 + (((idx >> 3) >= 4) ? 1 : 0)) : 0;
    int rw = (ww == 31) ? (1 + (((idx & 7)  >= 4) ? 1 : 0)) : 0;
    return rh*3 + rw;
}

__global__ __launch_bounds__(64) void attn_kernel()
{
    __shared__ __align__(16) float q_s[32][64];    // [d][n]
    __shared__ __align__(16) float k_s[32][64];    // [d][m]
    __shared__ __align__(16) float v_s[64][36];    // [m][d], padded
    __shared__ __align__(16) float p_s[64][64];    // probs [m][n]
    __shared__ float psum_s[64][9];                // row-sum partials

    int win  = blockIdx.x;
    int head = blockIdx.y;
    int tid  = threadIdx.x;
    int tn   = tid & 7;           // n-block  (n0 = 8*tn)
    int tm   = tid >> 3;          // m-block / d-block
    int n0   = tn*8, m0 = tm*8, d0 = tm*4;
    size_t base = (size_t)(win*3 + head) * 2048;

    const float4* qg = (const float4*)(g_q + base);
    const float4* kg = (const float4*)(g_k + base);
    const float4* vg = (const float4*)(g_v + base);
    for (int i = tid; i < 512; i += 64) {
        ((float4*)q_s)[i] = qg[i];                 // flat: [32][64] contiguous
        ((float4*)k_s)[i] = kg[i];
        int m = i >> 3, dq = i & 7;
        *(float4*)&v_s[m][dq*4] = vg[i];
    }
    __syncthreads();

    // ---- QK^T: thread computes 8x8 score tile ----
    float acc[8][8];
    #pragma unroll
    for (int i = 0; i < 8; i++)
        #pragma unroll
        for (int j = 0; j < 8; j++) acc[i][j] = 0.f;

    #pragma unroll 4
    for (int d = 0; d < 32; d++) {
        float4 qa = *(const float4*)&q_s[d][n0];
        float4 qb = *(const float4*)&q_s[d][n0 + 4];
        float4 ka = *(const float4*)&k_s[d][m0];
        float4 kb = *(const float4*)&k_s[d][m0 + 4];
        float qv[8] = {qa.x, qa.y, qa.z, qa.w, qb.x, qb.y, qb.z, qb.w};
        float kv[8] = {ka.x, ka.y, ka.z, ka.w, kb.x, kb.y, kb.z, kb.w};
        #pragma unroll
        for (int i = 0; i < 8; i++)
            #pragma unroll
            for (int j = 0; j < 8; j++)
                acc[i][j] = fmaf(qv[i], kv[j], acc[i][j]);
    }

    // ---- bias + mask + exp (no-max softmax; scores are O(1)) ----
    int wloc = win & 1023;
    int wh = wloc >> 5, ww = wloc & 31;
    bool masked = (wh == 31) || (ww == 31);
    int labn[8], labm[8];
    if (masked) {
        #pragma unroll
        for (int i = 0; i < 8; i++) {
            labn[i] = swin_label(wh, ww, n0 + i);
            labm[i] = swin_label(wh, ww, m0 + i);
        }
    }
    const float* bb = g_bias + head*4096;
    float lpart[8];
    #pragma unroll
    for (int i = 0; i < 8; i++) {
        float4 b0 = *(const float4*)&bb[(n0 + i)*64 + m0];
        float4 b1 = *(const float4*)&bb[(n0 + i)*64 + m0 + 4];
        float bv[8] = {b0.x, b0.y, b0.z, b0.w, b1.x, b1.y, b1.z, b1.w};
        float lp = 0.f;
        #pragma unroll
        for (int j = 0; j < 8; j++) {
            float p = __expf(acc[i][j] + bv[j]);
            if (masked && labm[j] != labn[i]) p = 0.f;
            acc[i][j] = p;
            lp += p;
        }
        lpart[i] = lp;
    }
    // stage probs (transposed [m][n]) + row-sum partials
    #pragma unroll
    for (int j = 0; j < 8; j++) {
        *(float4*)&p_s[m0 + j][n0] =
            make_float4(acc[0][j], acc[1][j], acc[2][j], acc[3][j]);
        *(float4*)&p_s[m0 + j][n0 + 4] =
            make_float4(acc[4][j], acc[5][j], acc[6][j], acc[7][j]);
    }
    #pragma unroll
    for (int i = 0; i < 8; i++) psum_s[n0 + i][tm] = lpart[i];
    __syncthreads();

    // ---- PV: thread computes 8n x 4d tile ----
    float out[8][4];
    #pragma unroll
    for (int i = 0; i < 8; i++)
        #pragma unroll
        for (int c = 0; c < 4; c++) out[i][c] = 0.f;

    #pragma unroll 4
    for (int m = 0; m < 64; m++) {
        float4 pa = *(const float4*)&p_s[m][n0];
        float4 pb = *(const float4*)&p_s[m][n0 + 4];
        float4 vv = *(const float4*)&v_s[m][d0];
        float pv[8] = {pa.x, pa.y, pa.z, pa.w, pb.x, pb.y, pb.z, pb.w};
        #pragma unroll
        for (int i = 0; i < 8; i++) {
            out[i][0] = fmaf(pv[i], vv.x, out[i][0]);
            out[i][1] = fmaf(pv[i], vv.y, out[i][1]);
            out[i][2] = fmaf(pv[i], vv.z, out[i][2]);
            out[i][3] = fmaf(pv[i], vv.w, out[i][3]);
        }
    }

    // ---- normalize + un-window + roll back, write channels-last ----
    int b = win >> 10;
    #pragma unroll
    for (int i = 0; i < 8; i++) {
        float l = 0.f;
        #pragma unroll
        for (int j = 0; j < 8; j++) l += psum_s[n0 + i][j];
        float inv = 1.f / l;
        int n = n0 + i;
        int r = n >> 3, c = n & 7;
        int h = ((wh << 3) + r + 4) & 255;
        int w = ((ww << 3) + c + 4) & 255;
        float* ap = g_att + ((size_t)(b*256 + h)*256 + w)*96 + head*32 + d0;
        *(float4*)ap = make_float4(out[i][0]*inv, out[i][1]*inv,
                                   out[i][2]*inv, out[i][3]*inv);
    }
}

// ---------------- kernel D: add (conv + attn), final 96x96 GEMM ------------
__global__ __launch_bounds__(256) void final_kernel(
    const float* __restrict__ Wp, const float* __restrict__ bp,
    float* __restrict__ outp)
{
    __shared__ float t_s[64][97];
    __shared__ float w_s[32][97];

    int t   = blockIdx.x;
    int b   = t >> 10;
    int hw0 = (t & 1023) << 6;
    int h   = hw0 >> 8;
    int tid = threadIdx.x;

    for (int idx = tid; idx < 96*16; idx += 256) {
        int c = idx >> 4, pq = idx & 15;
        float4 v4 = *(const float4*)&g_conv[((size_t)b*96 + c)*HW + hw0 + pq*4];
        t_s[pq*4 + 0][c] = v4.x;
        t_s[pq*4 + 1][c] = v4.y;
        t_s[pq*4 + 2][c] = v4.z;
        t_s[pq*4 + 3][c] = v4.w;
    }
    __syncthreads();

    const float* ab = g_att + ((size_t)(b*256 + h)*256 + (hw0 & 255))*96;
    for (int idx = tid; idx < 64*24; idx += 256) {
        int f4 = idx % 24, p = idx / 24;
        float4 a4 = *(const float4*)&ab[p*96 + f4*4];
        int c = f4*4;
        t_s[p][c]     += a4.x;
        t_s[p][c + 1] += a4.y;
        t_s[p][c + 2] += a4.z;
        t_s[p][c + 3] += a4.w;
    }
    __syncthreads();

    int pxg = tid & 15, chg = tid >> 4;
    int p0 = pxg*4, ob = chg*6;
    float acc[6][4];
    #pragma unroll
    for (int i = 0; i < 6; i++)
        #pragma unroll
        for (int j = 0; j < 4; j++) acc[i][j] = 0.f;

    for (int kc = 0; kc < 3; kc++) {
        if (kc) __syncthreads();
        for (int idx = tid; idx < 32*96; idx += 256) {
            int kk = idx & 31, o = idx >> 5;
            w_s[kk][o] = Wp[o*96 + kc*32 + kk];
        }
        __syncthreads();
        #pragma unroll 4
        for (int kk = 0; kk < 32; kk++) {
            int k = kc*32 + kk;
            float tv0 = t_s[p0][k],   tv1 = t_s[p0+1][k];
            float tv2 = t_s[p0+2][k], tv3 = t_s[p0+3][k];
            #pragma unroll
            for (int i = 0; i < 6; i++) {
                float wv = w_s[kk][ob + i];
                acc[i][0] = fmaf(wv, tv0, acc[i][0]);
                acc[i][1] = fmaf(wv, tv1, acc[i][1]);
                acc[i][2] = fmaf(wv, tv2, acc[i][2]);
                acc[i][3] = fmaf(wv, tv3, acc[i][3]);
            }
        }
    }

    #pragma unroll
    for (int i = 0; i < 6; i++) {
        int o = ob + i;
        float bo = bp[o];
        *(float4*)&outp[((size_t)b*96 + o)*HW + hw0 + p0] =
            make_float4(acc[i][0] + bo, acc[i][1] + bo,
                        acc[i][2] + bo, acc[i][3] + bo);
    }
}

// ---------------- launch ----------------------------------------------------
extern "C" void kernel_launch(void* const* d_in, const int* in_sizes, int n_in,
                              void* d_out, int out_size)
{
    const float* x   = (const float*)d_in[0];
    const float* Wv  = (const float*)d_in[1];
    const float* bv  = (const float*)d_in[2];
    const float* Wqk = (const float*)d_in[3];
    const float* bqk = (const float*)d_in[4];
    const float* Wm1 = (const float*)d_in[5];
    const float* bm1 = (const float*)d_in[6];
    const float* Wm2 = (const float*)d_in[7];
    const float* bm2 = (const float*)d_in[8];
    const float* Wdw = (const float*)d_in[9];
    const float* bdw = (const float*)d_in[10];
    const float* Wp  = (const float*)d_in[11];
    const float* bp  = (const float*)d_in[12];
    float* outp = (float*)d_out;

    bias_kernel <<<16, 256>>>(Wm1, bm1, Wm2, bm2);
    qkv_kernel  <<<dim3(4096, 6), 128>>>(x, Wqk, bqk, Wv, bv);
    dw_kernel   <<<24576, 256>>>(Wdw, bdw);
    attn_kernel <<<dim3(4096, 3), 64>>>();
    final_kernel<<<4096, 256>>>(Wp, bp, outp);
}